// round 14
// baseline (speedup 1.0000x reference)
#include <cuda_runtime.h>
#include <cuda_bf16.h>
#include <stdint.h>
#include <math.h>

#define Bn 8
#define Cn 128
#define Hn 224
#define Wn 224
#define HWn (Hn*Wn)        // 50176
#define CHWn (Cn*HWn)      // 6422528
#define NPIX (Bn*HWn)      // 401408

// ---------------- scratch (static device globals; no allocation) ----------------
__device__ float g_y[(long long)Bn*CHWn];   // LN2-normalized, shuffled tensor (205.5 MB)
__device__ float g_m1[NPIX];
__device__ float g_r1[NPIX];
__device__ float g_spw_w[4*32*32];   // [g][o][c], group order (s2,s4,s1,s3)
__device__ float g_spw_wT[4*32*32];  // [g][c][o]  (filled by k0_prep)
__device__ float g_spw_b[128];
__device__ float g_c5w[128*9];
__device__ float g_c5b[128];
__device__ float g_n2w[128];
__device__ float g_n2b[128];
// final pw weights, bf16 hi/lo split, plain [o][ch] layout (filled by k0_prep)
__device__ __align__(16) unsigned short g_pwbh[Cn*Cn];
__device__ __align__(16) unsigned short g_pwbl[Cn*Cn];

// ---------------- constant weights (warp-uniform access only) ----------------
__constant__ float c_n1w[Cn], c_n1b[Cn];
__constant__ float c_sdw_w[4][32][9];
__constant__ float c_sdw_b[4][32];
__constant__ float c_ldww[Cn][9];
__constant__ float c_ldwb[Cn];
__constant__ float c_lpwb[Cn];

__device__ __forceinline__ float gelu_exact(float x) {
    return 0.5f * x * (1.0f + erff(x * 0.70710678118654752f));
}

// split fp32 -> bf16 hi + bf16 lo
__device__ __forceinline__ void bf16_split(float v, unsigned short& hb, unsigned short& lb) {
    __nv_bfloat16 h = __float2bfloat16(v);
    float hf = __bfloat162float(h);
    __nv_bfloat16 l = __float2bfloat16(v - hf);
    hb = *(unsigned short*)&h;
    lb = *(unsigned short*)&l;
}

// warp-level bf16 MMA (sm_80+ path, valid on base sm_100)
__device__ __forceinline__ void mma16816(float* c, const uint32_t* a, const uint32_t* b) {
    asm volatile(
        "mma.sync.aligned.m16n8k16.row.col.f32.bf16.bf16.f32 "
        "{%0,%1,%2,%3}, {%4,%5,%6,%7}, {%8,%9}, {%0,%1,%2,%3};"
        : "+f"(c[0]), "+f"(c[1]), "+f"(c[2]), "+f"(c[3])
        : "r"(a[0]), "r"(a[1]), "r"(a[2]), "r"(a[3]), "r"(b[0]), "r"(b[1]));
}

// ================= kernel 0: prep weights =================
__global__ __launch_bounds__(256) void k0_prep(const float* __restrict__ pw)
{
    int i = blockIdx.x * 256 + threadIdx.x;
    if (i < Cn*Cn) {
        unsigned short hb, lb;
        bf16_split(pw[i], hb, lb);
        g_pwbh[i] = hb;      // [o][ch] row-major
        g_pwbl[i] = lb;
    }
    if (i < 4096) {
        int g = i >> 10, r = i & 1023, o = r >> 5, c = r & 31;
        g_spw_wT[g*1024 + c*32 + o] = g_spw_w[i];
    }
}

// ================= kernel 1: LN1 stats =================
__global__ __launch_bounds__(256) void k1_stats(const float* __restrict__ x)
{
    int idx = blockIdx.x * 256 + threadIdx.x;
    int b  = idx / HWn;
    int hw = idx - b * HWn;
    const float* px = x + b * CHWn + hw;
    float s = 0.f, ss = 0.f;
    #pragma unroll 8
    for (int ch = 0; ch < Cn; ch++) {
        float v = px[ch * HWn];
        s += v; ss = fmaf(v, v, ss);
    }
    float m = s * (1.0f/128.0f);
    float var = fmaf(-m, m, ss * (1.0f/128.0f));
    g_m1[idx] = m;
    g_r1[idx] = rsqrtf(var + 1e-6f);
}

// ================= kernel 2: branches + c5 + shuffle + LN2 (1024 threads) =================
#define T2W 16
#define T2H 8
#define R2W 20
#define R2H 12
#define NPOS 240           // R2H*R2W
#define NT2 1024
#define OFF_SX   0                       // [128][240]
#define OFF_ST   (OFF_SX + Cn*NPOS)      // 30720: t [128][128]
#define OFF_W2   (OFF_ST + Cn*128)       // 47104: spw_wT [4][32c][32o]
#define OFF_RED  (OFF_W2 + 4096)         // 51200: [2][4][128]
#define OFF_MS   (OFF_RED + 1024)        // 52224
#define OFF_RS   (OFF_MS + 128)
#define OFF_GAM  (OFF_RS + 128)
#define OFF_BET  (OFF_GAM + 128)
#define OFF_C5W  (OFF_BET + 128)         // [128][9]
#define OFF_C5B  (OFF_C5W + 1152)
#define OFF_PWB  (OFF_C5B + 128)
#define OFF_SM1  (OFF_PWB + 128)         // [240]
#define OFF_SR1  (OFF_SM1 + NPOS)
#define SMEM2_FLOATS (OFF_SR1 + NPOS)    // 54624 floats = 218496 B

__global__ __launch_bounds__(NT2, 1) void k2_mix(const float* __restrict__ x)
{
    extern __shared__ float sm[];
    const int b  = blockIdx.z;
    const int h0 = blockIdx.y * T2H;
    const int w0 = blockIdx.x * T2W;
    const int tid = threadIdx.x;
    const int wid = tid >> 5, lane = tid & 31;
    const long long xb = (long long)b * CHWn;

    if (tid < NPOS) {
        int r = tid / R2W, cc = tid - r * R2W;
        int gh = h0 + r - 2, gw = w0 + cc - 2;
        float m = 0.f, rs = 0.f;
        if ((unsigned)gh < (unsigned)Hn && (unsigned)gw < (unsigned)Wn) {
            int p = b * HWn + gh * Wn + gw;
            m = g_m1[p]; rs = g_r1[p];
        }
        sm[OFF_SM1 + tid] = m; sm[OFF_SR1 + tid] = rs;
    }
    for (int i = tid; i < 4096; i += NT2) sm[OFF_W2 + i] = g_spw_wT[i];
    for (int i = tid; i < 1152; i += NT2) sm[OFF_C5W + i] = g_c5w[i];
    if (tid < 128) {
        sm[OFF_C5B + tid] = g_c5b[tid];
        sm[OFF_PWB + tid] = g_spw_b[tid];
        sm[OFF_GAM + tid] = g_n2w[tid];
        sm[OFF_BET + tid] = g_n2b[tid];
    }
    __syncthreads();

    // ---- stage LN1(x) tile: hoisted per-pos metadata, warp-per-channel ----
    {
        int   gofs[8];
        float mV[8], rV[8];
        #pragma unroll
        for (int j = 0; j < 8; j++) {
            int pos = lane + 32 * j;
            bool ok = pos < NPOS;
            int r = pos / R2W, cc = pos - r * R2W;
            int gh = h0 + r - 2, gw = w0 + cc - 2;
            bool inb = ok && (unsigned)gh < (unsigned)Hn && (unsigned)gw < (unsigned)Wn;
            gofs[j] = inb ? (gh * Wn + gw) : -1;
            mV[j] = ok ? sm[OFF_SM1 + pos] : 0.f;
            rV[j] = ok ? sm[OFF_SR1 + pos] : 0.f;
        }
        for (int k = 0; k < 4; k++) {
            const int ch = wid + 32 * k;                  // warp-uniform
            const float gam = c_n1w[ch], bet = c_n1b[ch];
            const float* xc = x + xb + (long long)ch * HWn;
            #pragma unroll
            for (int j = 0; j < 8; j++) {
                int pos = lane + 32 * j;
                if (pos < NPOS) {
                    float v = 0.f;
                    if (gofs[j] >= 0) v = (xc[gofs[j]] - mV[j]) * rV[j] * gam + bet;
                    sm[OFF_SX + ch * NPOS + pos] = v;
                }
            }
        }
    }
    __syncthreads();

    // ---- phase B: pixel-pair dw3+gelu, 8 ch-iters ----
    {
        const int pairslot = tid & 63;
        const int px0 = pairslot & 15, py0 = (pairslot >> 4) * 2;
        const int chb = tid >> 6;                          // 0..15, warp-uniform
        bool myp[4], mx[3];
        #pragma unroll
        for (int k = 0; k < 4; k++) myp[k] = (unsigned)(h0 + py0 + k - 1) < (unsigned)Hn;
        #pragma unroll
        for (int d = 0; d < 3; d++)  mx[d]  = (unsigned)(w0 + px0 + d - 1) < (unsigned)Wn;

        #pragma unroll 2
        for (int it = 0; it < 8; it++) {
            const int ch = chb + it * 16;                  // warp-uniform
            const int gg = ch >> 5, cc = ch & 31;
            const int srcb = ((0x2031 >> (4*gg)) & 15) << 5;   // {32,96,0,64}
            const int offy = (0x2002 >> (4*gg)) & 15;          // 1 - shh
            const int offx = (0x2020 >> (4*gg)) & 15;          // 1 - shw
            const float* bp = sm + OFF_SX + (srcb + cc) * NPOS + (py0 + offy) * R2W + (px0 + offx);
            float aA = c_sdw_b[gg][cc], aB = aA;
            #pragma unroll
            for (int k = 0; k < 4; k++) {
                #pragma unroll
                for (int d = 0; d < 3; d++) {
                    float t = bp[k * R2W + d];
                    bool okc = myp[k] && mx[d];
                    if (k < 3 && okc) aA = fmaf(c_sdw_w[gg][cc][k*3 + d], t, aA);
                    if (k > 0 && okc) aB = fmaf(c_sdw_w[gg][cc][(k-1)*3 + d], t, aB);
                }
            }
            sm[OFF_ST + ch * 128 + py0 * 16 + px0]       = gelu_exact(aA);
            sm[OFF_ST + ch * 128 + (py0 + 1) * 16 + px0] = gelu_exact(aB);
        }
    }
    __syncthreads();

    // ---- phase C: pw GEMM (block-diag 32x32) + c5 residual + LN2 ----
    const int g    = tid >> 8;             // 0..3, warp-uniform group
    const int oj   = tid & 7;              // o sub-slot (4 o each)
    const int qslot = (tid >> 3) & 31;
    const int qpix = qslot * 4;
    const int qy = qpix >> 4, qx = qpix & 15;

    float acc[4][4];
    #pragma unroll
    for (int j = 0; j < 4; j++) {
        float bj = sm[OFF_PWB + g * 32 + oj * 4 + j];
        acc[j][0] = bj; acc[j][1] = bj; acc[j][2] = bj; acc[j][3] = bj;
    }
    {
        const float* w2g = sm + OFF_W2 + g * 1024 + oj * 4;
        const float* stg = sm + OFF_ST + (g * 32) * 128 + qpix;
        #pragma unroll 8
        for (int c = 0; c < 32; c++) {
            float4 wa = *(const float4*)(w2g + c * 32);
            float4 tv = *(const float4*)(stg + c * 128);
            acc[0][0]=fmaf(wa.x,tv.x,acc[0][0]); acc[0][1]=fmaf(wa.x,tv.y,acc[0][1]); acc[0][2]=fmaf(wa.x,tv.z,acc[0][2]); acc[0][3]=fmaf(wa.x,tv.w,acc[0][3]);
            acc[1][0]=fmaf(wa.y,tv.x,acc[1][0]); acc[1][1]=fmaf(wa.y,tv.y,acc[1][1]); acc[1][2]=fmaf(wa.y,tv.z,acc[1][2]); acc[1][3]=fmaf(wa.y,tv.w,acc[1][3]);
            acc[2][0]=fmaf(wa.z,tv.x,acc[2][0]); acc[2][1]=fmaf(wa.z,tv.y,acc[2][1]); acc[2][2]=fmaf(wa.z,tv.z,acc[2][2]); acc[2][3]=fmaf(wa.z,tv.w,acc[2][3]);
            acc[3][0]=fmaf(wa.w,tv.x,acc[3][0]); acc[3][1]=fmaf(wa.w,tv.y,acc[3][1]); acc[3][2]=fmaf(wa.w,tv.z,acc[3][2]); acc[3][3]=fmaf(wa.w,tv.w,acc[3][3]);
        }
    }
    // c5 residual (unshifted dw3 of LN1(x); zero halo = SAME pad)
    #pragma unroll
    for (int j = 0; j < 4; j++) {
        const int ci = g * 32 + oj * 4 + j;
        const float* cw = sm + OFF_C5W + ci * 9;
        const float* bp = sm + OFF_SX + ci * NPOS + (qy + 1) * R2W + (qx + 1);
        const float b5 = sm[OFF_C5B + ci];
        #pragma unroll
        for (int i = 0; i < 4; i++) {
            float a5 = b5;
            #pragma unroll
            for (int k = 0; k < 9; k++)
                a5 = fmaf(cw[k], bp[(k/3)*R2W + (k%3) + i], a5);
            acc[j][i] += a5;
        }
    }
    // ---- LN2 stats: shfl over oj (lane bits 0-2), then tiny cross-g smem pass ----
    {
        float ps[4] = {0,0,0,0}, pq[4] = {0,0,0,0};
        #pragma unroll
        for (int j = 0; j < 4; j++)
            #pragma unroll
            for (int i = 0; i < 4; i++) { ps[i] += acc[j][i]; pq[i] = fmaf(acc[j][i], acc[j][i], pq[i]); }
        #pragma unroll
        for (int d = 1; d <= 4; d <<= 1) {
            #pragma unroll
            for (int i = 0; i < 4; i++) {
                ps[i] += __shfl_xor_sync(0xFFFFFFFFu, ps[i], d);
                pq[i] += __shfl_xor_sync(0xFFFFFFFFu, pq[i], d);
            }
        }
        if (oj == 0) {
            *(float4*)&sm[OFF_RED + g * 128 + qpix]       = make_float4(ps[0], ps[1], ps[2], ps[3]);
            *(float4*)&sm[OFF_RED + 512 + g * 128 + qpix] = make_float4(pq[0], pq[1], pq[2], pq[3]);
        }
    }
    __syncthreads();
    if (tid < 128) {
        float s = 0.f, ss = 0.f;
        #pragma unroll
        for (int g2 = 0; g2 < 4; g2++) {
            s  += sm[OFF_RED + g2 * 128 + tid];
            ss += sm[OFF_RED + 512 + g2 * 128 + tid];
        }
        float m = s * (1.0f/128.0f);
        float var = fmaf(-m, m, ss * (1.0f/128.0f));
        sm[OFF_MS + tid] = m;
        sm[OFF_RS + tid] = rsqrtf(var + 1e-6f);
    }
    __syncthreads();

    float mv[4], rv[4];
    #pragma unroll
    for (int i = 0; i < 4; i++) { mv[i] = sm[OFF_MS + qpix + i]; rv[i] = sm[OFF_RS + qpix + i]; }
    const long long obase = xb + (long long)(h0 + qy) * Wn + (w0 + qx);
    #pragma unroll
    for (int j = 0; j < 4; j++) {
        const int ci = g * 32 + oj * 4 + j;
        const int ko = ((ci & 63) << 1) | (ci >> 6);   // channel shuffle, 2 groups
        const float gam = sm[OFF_GAM + ko], bet = sm[OFF_BET + ko];
        float4 ov;
        ov.x = fmaf((acc[j][0] - mv[0]) * rv[0], gam, bet);
        ov.y = fmaf((acc[j][1] - mv[1]) * rv[1], gam, bet);
        ov.z = fmaf((acc[j][2] - mv[2]) * rv[2], gam, bet);
        ov.w = fmaf((acc[j][3] - mv[3]) * rv[3], gam, bet);
        *(float4*)&g_y[obase + (long long)ko * HWn] = ov;
    }
}

// ================= kernel 3: dw3(gelu) + mma.sync bf16-split GEMM (1024 threads) =================
#define T3W 16
#define T3H 8
#define R3H 10
#define R3W 18
#define NT3 1024
#define YCH 32                         // channels per staging chunk
#define YPOS (R3H*R3W)                 // 180
#define AS3 136                        // bf16 row stride (272B): conflict-free frags
#define SM3_AH   0
#define SM3_AL   (SM3_AH + 128*AS3*2)   // 34816
#define SM3_BH   (SM3_AL + 128*AS3*2)   // 69632
#define SM3_BL   (SM3_BH + 128*AS3*2)   // 104448
#define SM3_Y    (SM3_BL + 128*AS3*2)   // 139264: 2 x [32][180] fp32
#define SM3_BIAS (SM3_Y + 2*YCH*YPOS*4) // 185344
#define SM3_TOTAL (SM3_BIAS + 512)      // 185856 bytes

__global__ __launch_bounds__(NT3, 1) void k3_final(float* __restrict__ out)
{
    extern __shared__ char smc[];
    float* bias = (float*)(smc + SM3_BIAS);
    const int b  = blockIdx.z;
    const int h0 = blockIdx.y * T3H;
    const int w0 = blockIdx.x * T3W;
    const int tid = threadIdx.x;
    const int wid = tid >> 5, lane = tid & 31;
    const long long xb = (long long)b * CHWn;
    float* ybuf0 = (float*)(smc + SM3_Y);
    float* ybuf1 = ybuf0 + YCH * YPOS;

    // stage B hi/lo (long-latency loads issue first)
    for (int i = tid; i < 4096; i += NT3) {
        int o = i >> 5, qq = i & 31;
        *(uint2*)(smc + SM3_BH + o * (AS3*2) + qq * 8) = ((const uint2*)g_pwbh)[i];
        *(uint2*)(smc + SM3_BL + o * (AS3*2) + qq * 8) = ((const uint2*)g_pwbl)[i];
    }
    if (tid < 128) bias[tid] = c_lpwb[tid];

    // hoisted per-lane staging metadata for pos = lane + 32*j (j<6)
    int goff[6];
    #pragma unroll
    for (int j = 0; j < 6; j++) {
        int pos = lane + 32 * j;
        bool ok = pos < YPOS;
        int r = pos / R3W, cc = pos - r * R3W;
        int gh = h0 + r - 1, gw = w0 + cc - 1;
        bool inb = ok && (unsigned)gh < (unsigned)Hn && (unsigned)gw < (unsigned)Wn;
        goff[j] = inb ? (gh * Wn + gw) : -1;
    }

    // stage chunk 0 into ybuf0 (one channel per warp)
    if (wid < YCH) {
        const float* yc = g_y + xb + (long long)wid * HWn;
        float* dst = ybuf0 + wid * YPOS;
        #pragma unroll
        for (int j = 0; j < 6; j++) {
            int pos = lane + 32 * j;
            if (pos < YPOS) dst[pos] = (goff[j] >= 0) ? yc[goff[j]] : 0.f;
        }
    }
    __syncthreads();

    #pragma unroll
    for (int q = 0; q < 4; q++) {
        float* cur = (q & 1) ? ybuf1 : ybuf0;
        float* nxt = (q & 1) ? ybuf0 : ybuf1;
        // issue next chunk's loads first (overlap with compute below)
        if (q < 3 && wid < YCH) {
            const int chb = (q + 1) * YCH;
            const float* yc = g_y + xb + (long long)(chb + wid) * HWn;
            float* dst = nxt + wid * YPOS;
            #pragma unroll
            for (int j = 0; j < 6; j++) {
                int pos = lane + 32 * j;
                if (pos < YPOS) dst[pos] = (goff[j] >= 0) ? yc[goff[j]] : 0.f;
            }
        }
        // compute chunk q: 8 ch-groups (4 ch each) x 128 px = 1024 threads
        {
            const int p = tid & 127;
            const int py = p >> 4, pxx = p & 15;
            const int grp = tid >> 7;                     // 0..7, warp-uniform
            const int chl0 = grp * 4;
            const int ch0 = q * YCH + chl0;
            uint32_t hv[2], lv[2];
            #pragma unroll
            for (int j = 0; j < 4; j++) {
                const int ch = ch0 + j;
                const float* bp = cur + (chl0 + j) * YPOS + py * R3W + pxx;
                float a = c_ldwb[ch];
                #pragma unroll
                for (int k = 0; k < 9; k++)
                    a = fmaf(c_ldww[ch][k], bp[(k/3)*R3W + (k%3)], a);
                float v = gelu_exact(a);
                unsigned short hb, lb;
                bf16_split(v, hb, lb);
                if (j & 1) { hv[j >> 1] |= (uint32_t)hb << 16; lv[j >> 1] |= (uint32_t)lb << 16; }
                else       { hv[j >> 1]  = hb;                 lv[j >> 1]  = lb; }
            }
            *(uint2*)(smc + SM3_AH + p * (AS3*2) + ch0 * 2) = make_uint2(hv[0], hv[1]);
            *(uint2*)(smc + SM3_AL + p * (AS3*2) + ch0 * 2) = make_uint2(lv[0], lv[1]);
        }
        __syncthreads();
    }

    // warp GEMM: 32 warps, 16(M) x 32(N) tile each; 3 passes (AhBh, AhBl, AlBh)
    const int mi = wid >> 2, ni = wid & 3;     // mi 0..7 (m16), ni 0..3 (n32)
    const int lr = lane >> 2, lc = lane & 3;
    float cfr[4][4];
    #pragma unroll
    for (int t = 0; t < 4; t++) { cfr[t][0]=0.f; cfr[t][1]=0.f; cfr[t][2]=0.f; cfr[t][3]=0.f; }

    #pragma unroll
    for (int pass = 0; pass < 3; pass++) {
        const char* Ab = smc + (pass == 2 ? SM3_AL : SM3_AH);
        const char* Bb = smc + (pass == 1 ? SM3_BL : SM3_BH);
        #pragma unroll
        for (int k0 = 0; k0 < 8; k0++) {
            const int kb = k0 * 16;
            uint32_t a[4], bfr[4][2];
            {
                const char* ap = Ab + (mi*16 + lr) * (AS3*2) + (kb + lc*2) * 2;
                a[0] = *(const uint32_t*)(ap);
                a[1] = *(const uint32_t*)(ap + 8 * (AS3*2));
                a[2] = *(const uint32_t*)(ap + 16);
                a[3] = *(const uint32_t*)(ap + 8 * (AS3*2) + 16);
            }
            #pragma unroll
            for (int n4 = 0; n4 < 4; n4++) {
                const char* bp = Bb + (ni*32 + n4*8 + lr) * (AS3*2) + (kb + lc*2) * 2;
                bfr[n4][0] = *(const uint32_t*)(bp);
                bfr[n4][1] = *(const uint32_t*)(bp + 16);
            }
            #pragma unroll
            for (int n4 = 0; n4 < 4; n4++)
                mma16816(cfr[n4], a, bfr[n4]);
        }
    }

    // epilogue: add bias, store direct to gmem
    #pragma unroll
    for (int n4 = 0; n4 < 4; n4++) {
        const float* cf = cfr[n4];
        const int p0 = mi*16 + lr;
        const int p1 = p0 + 8;
        const int oo = ni*32 + n4*8 + lc*2;
        const float b0v = bias[oo], b1v = bias[oo + 1];
        const long long r0 = xb + (long long)(h0 + (p0 >> 4)) * Wn + (w0 + (p0 & 15));
        const long long r1 = xb + (long long)(h0 + (p1 >> 4)) * Wn + (w0 + (p1 & 15));
        out[r0 + (long long)oo * HWn]       = cf[0] + b0v;
        out[r0 + (long long)(oo+1) * HWn]   = cf[1] + b1v;
        out[r1 + (long long)oo * HWn]       = cf[2] + b0v;
        out[r1 + (long long)(oo+1) * HWn]   = cf[3] + b1v;
    }
}

// ================= launch =================
extern "C" void kernel_launch(void* const* d_in, const int* in_sizes, int n_in,
                              void* d_out, int out_size)
{
    (void)out_size;
    int idx_x = 0, idx_lpw = -1, idx_c5w = -1, idx_ldww = -1;
    int dw_w[4] = {-1,-1,-1,-1}, pw_w[4] = {-1,-1,-1,-1};
    int ndw = 0, npw = 0;
    for (int i = 0; i < n_in; i++) {
        int s = in_sizes[i];
        if (s > 100000)      idx_x = i;
        else if (s == 16384) idx_lpw = i;
        else if (s == 1152)  { if (idx_c5w < 0) idx_c5w = i; else idx_ldww = i; }
        else if (s == 288 && ndw < 4)  dw_w[ndw++] = i;
        else if (s == 1024 && npw < 4) pw_w[npw++] = i;
    }
    const int idx_c5b  = idx_c5w  + 1;
    const int idx_ldwb = idx_ldww + 1;
    const int idx_lpwb = idx_lpw  + 1;
    int v128[8]; int nv = 0;
    for (int i = 0; i < n_in; i++)
        if (in_sizes[i] == 128 && i != idx_c5b && i != idx_ldwb && i != idx_lpwb && nv < 8)
            v128[nv++] = i;
    const int idx_n1w = v128[0], idx_n1b = v128[1];
    const int idx_n2w = v128[2], idx_n2b = v128[3];

    const float* x = (const float*)d_in[idx_x];

    cudaMemcpyToSymbolAsync(c_n1w, d_in[idx_n1w], Cn*4, 0, cudaMemcpyDeviceToDevice);
    cudaMemcpyToSymbolAsync(c_n1b, d_in[idx_n1b], Cn*4, 0, cudaMemcpyDeviceToDevice);
    const int GS[4] = {1, 3, 0, 2};
    for (int g = 0; g < 4; g++) {
        int sbx = GS[g];
        cudaMemcpyToSymbolAsync(c_sdw_w,  d_in[dw_w[sbx]],     32*9*4,  g*32*9*4,  cudaMemcpyDeviceToDevice);
        cudaMemcpyToSymbolAsync(c_sdw_b,  d_in[dw_w[sbx] + 1], 32*4,    g*32*4,    cudaMemcpyDeviceToDevice);
        cudaMemcpyToSymbolAsync(g_spw_w,  d_in[pw_w[sbx]],     32*32*4, g*32*32*4, cudaMemcpyDeviceToDevice);
        cudaMemcpyToSymbolAsync(g_spw_b,  d_in[pw_w[sbx] + 1], 32*4,    g*32*4,    cudaMemcpyDeviceToDevice);
    }
    cudaMemcpyToSymbolAsync(g_c5w,  d_in[idx_c5w],  Cn*9*4, 0, cudaMemcpyDeviceToDevice);
    cudaMemcpyToSymbolAsync(g_c5b,  d_in[idx_c5b],  Cn*4,   0, cudaMemcpyDeviceToDevice);
    cudaMemcpyToSymbolAsync(g_n2w,  d_in[idx_n2w],  Cn*4,   0, cudaMemcpyDeviceToDevice);
    cudaMemcpyToSymbolAsync(g_n2b,  d_in[idx_n2b],  Cn*4,   0, cudaMemcpyDeviceToDevice);
    cudaMemcpyToSymbolAsync(c_ldww, d_in[idx_ldww], Cn*9*4, 0, cudaMemcpyDeviceToDevice);
    cudaMemcpyToSymbolAsync(c_ldwb, d_in[idx_ldwb], Cn*4,   0, cudaMemcpyDeviceToDevice);
    cudaMemcpyToSymbolAsync(c_lpwb, d_in[idx_lpwb], Cn*4,   0, cudaMemcpyDeviceToDevice);

    const int smem2 = SMEM2_FLOATS * 4;
    cudaFuncSetAttribute(k2_mix,   cudaFuncAttributeMaxDynamicSharedMemorySize, smem2);
    cudaFuncSetAttribute(k3_final, cudaFuncAttributeMaxDynamicSharedMemorySize, SM3_TOTAL);

    k0_prep<<<64, 256>>>((const float*)d_in[idx_lpw]);
    k1_stats<<<NPIX/256, 256>>>(x);
    k2_mix<<<dim3(Wn/T2W, Hn/T2H, Bn), NT2, smem2>>>(x);
    k3_final<<<dim3(Wn/T3W, Hn/T3H, Bn), NT3, SM3_TOTAL>>>((float*)d_out);
}

// round 15
// speedup vs baseline: 1.0539x; 1.0539x over previous
#include <cuda_runtime.h>
#include <cuda_bf16.h>
#include <stdint.h>
#include <math.h>

#define Bn 8
#define Cn 128
#define Hn 224
#define Wn 224
#define HWn (Hn*Wn)        // 50176
#define CHWn (Cn*HWn)      // 6422528
#define NPIX (Bn*HWn)      // 401408

// ---------------- scratch (static device globals; no allocation) ----------------
__device__ float g_y[(long long)Bn*CHWn];   // LN2-normalized, shuffled tensor (205.5 MB)
__device__ float g_m1[NPIX];
__device__ float g_r1[NPIX];
__device__ float g_spw_w[4*32*32];   // [g][o][c], group order (s2,s4,s1,s3)
__device__ float g_spw_wT[4*32*32];  // [g][c][o]  (filled by k0_prep)
__device__ float g_spw_b[128];
__device__ float g_c5w[128*9];
__device__ float g_c5b[128];
__device__ float g_n2w[128];
__device__ float g_n2b[128];
// final pw weights, bf16 hi/lo split, plain [o][ch] layout (filled by k0_prep)
__device__ __align__(16) unsigned short g_pwbh[Cn*Cn];
__device__ __align__(16) unsigned short g_pwbl[Cn*Cn];

// ---------------- constant weights (warp-uniform access only) ----------------
__constant__ float c_n1w[Cn], c_n1b[Cn];
__constant__ float c_sdw_w[4][32][9];
__constant__ float c_sdw_b[4][32];
__constant__ float c_ldww[Cn][9];
__constant__ float c_ldwb[Cn];
__constant__ float c_lpwb[Cn];

__device__ __forceinline__ float gelu_exact(float x) {
    return 0.5f * x * (1.0f + erff(x * 0.70710678118654752f));
}

// split fp32 -> bf16 hi + bf16 lo
__device__ __forceinline__ void bf16_split(float v, unsigned short& hb, unsigned short& lb) {
    __nv_bfloat16 h = __float2bfloat16(v);
    float hf = __bfloat162float(h);
    __nv_bfloat16 l = __float2bfloat16(v - hf);
    hb = *(unsigned short*)&h;
    lb = *(unsigned short*)&l;
}

// warp-level bf16 MMA (sm_80+ path, valid on base sm_100)
__device__ __forceinline__ void mma16816(float* c, const uint32_t* a, const uint32_t* b) {
    asm volatile(
        "mma.sync.aligned.m16n8k16.row.col.f32.bf16.bf16.f32 "
        "{%0,%1,%2,%3}, {%4,%5,%6,%7}, {%8,%9}, {%0,%1,%2,%3};"
        : "+f"(c[0]), "+f"(c[1]), "+f"(c[2]), "+f"(c[3])
        : "r"(a[0]), "r"(a[1]), "r"(a[2]), "r"(a[3]), "r"(b[0]), "r"(b[1]));
}

__device__ __forceinline__ void ldsm_x4(uint32_t& r0, uint32_t& r1, uint32_t& r2, uint32_t& r3,
                                        uint32_t addr) {
    asm volatile("ldmatrix.sync.aligned.m8n8.x4.shared.b16 {%0,%1,%2,%3}, [%4];"
                 : "=r"(r0), "=r"(r1), "=r"(r2), "=r"(r3) : "r"(addr));
}
__device__ __forceinline__ uint32_t smem_u32(const void* p) {
    uint32_t a;
    asm("{ .reg .u64 t; cvta.to.shared.u64 t, %1; cvt.u32.u64 %0, t; }" : "=r"(a) : "l"(p));
    return a;
}

// ================= kernel 0: prep weights =================
__global__ __launch_bounds__(256) void k0_prep(const float* __restrict__ pw)
{
    int i = blockIdx.x * 256 + threadIdx.x;
    if (i < Cn*Cn) {
        unsigned short hb, lb;
        bf16_split(pw[i], hb, lb);
        g_pwbh[i] = hb;      // [o][ch] row-major
        g_pwbl[i] = lb;
    }
    if (i < 4096) {
        int g = i >> 10, r = i & 1023, o = r >> 5, c = r & 31;
        g_spw_wT[g*1024 + c*32 + o] = g_spw_w[i];
    }
}

// ================= kernel 1: LN1 stats =================
__global__ __launch_bounds__(256) void k1_stats(const float* __restrict__ x)
{
    int idx = blockIdx.x * 256 + threadIdx.x;
    int b  = idx / HWn;
    int hw = idx - b * HWn;
    const float* px = x + b * CHWn + hw;
    float s = 0.f, ss = 0.f;
    #pragma unroll 8
    for (int ch = 0; ch < Cn; ch++) {
        float v = px[ch * HWn];
        s += v; ss = fmaf(v, v, ss);
    }
    float m = s * (1.0f/128.0f);
    float var = fmaf(-m, m, ss * (1.0f/128.0f));
    g_m1[idx] = m;
    g_r1[idx] = rsqrtf(var + 1e-6f);
}

// ================= kernel 2: branches + c5 + shuffle + LN2 (reverted to R13: 512 thr) =================
#define T2W 16
#define T2H 8
#define R2W 20
#define R2H 12
#define NPOS 240           // R2H*R2W
#define NT2 512
#define OFF_SX   0                       // [128][240]
#define OFF_ST   (OFF_SX + Cn*NPOS)      // 30720: t [128][128]
#define OFF_W2   (OFF_ST + Cn*128)       // 47104: spw_wT [4][32c][32o]
#define OFF_RED  (OFF_W2 + 4096)         // 51200: [2][4][128]
#define OFF_MS   (OFF_RED + 1024)        // 52224
#define OFF_RS   (OFF_MS + 128)
#define OFF_GAM  (OFF_RS + 128)
#define OFF_BET  (OFF_GAM + 128)
#define OFF_C5W  (OFF_BET + 128)         // [128][9]
#define OFF_C5B  (OFF_C5W + 1152)
#define OFF_PWB  (OFF_C5B + 128)
#define OFF_SM1  (OFF_PWB + 128)         // [240]
#define OFF_SR1  (OFF_SM1 + NPOS)
#define SMEM2_FLOATS (OFF_SR1 + NPOS)    // 54624 floats = 218496 B

__global__ __launch_bounds__(NT2, 1) void k2_mix(const float* __restrict__ x)
{
    extern __shared__ float sm[];
    const int b  = blockIdx.z;
    const int h0 = blockIdx.y * T2H;
    const int w0 = blockIdx.x * T2W;
    const int tid = threadIdx.x;
    const int wid = tid >> 5, lane = tid & 31;
    const long long xb = (long long)b * CHWn;

    if (tid < NPOS) {
        int r = tid / R2W, cc = tid - r * R2W;
        int gh = h0 + r - 2, gw = w0 + cc - 2;
        float m = 0.f, rs = 0.f;
        if ((unsigned)gh < (unsigned)Hn && (unsigned)gw < (unsigned)Wn) {
            int p = b * HWn + gh * Wn + gw;
            m = g_m1[p]; rs = g_r1[p];
        }
        sm[OFF_SM1 + tid] = m; sm[OFF_SR1 + tid] = rs;
    }
    for (int i = tid; i < 4096; i += NT2) sm[OFF_W2 + i] = g_spw_wT[i];
    for (int i = tid; i < 1152; i += NT2) sm[OFF_C5W + i] = g_c5w[i];
    if (tid < 128) {
        sm[OFF_C5B + tid] = g_c5b[tid];
        sm[OFF_PWB + tid] = g_spw_b[tid];
        sm[OFF_GAM + tid] = g_n2w[tid];
        sm[OFF_BET + tid] = g_n2b[tid];
    }
    __syncthreads();

    {
        int   gofs[8];
        float mV[8], rV[8];
        #pragma unroll
        for (int j = 0; j < 8; j++) {
            int pos = lane + 32 * j;
            bool ok = pos < NPOS;
            int r = pos / R2W, cc = pos - r * R2W;
            int gh = h0 + r - 2, gw = w0 + cc - 2;
            bool inb = ok && (unsigned)gh < (unsigned)Hn && (unsigned)gw < (unsigned)Wn;
            gofs[j] = inb ? (gh * Wn + gw) : -1;
            mV[j] = ok ? sm[OFF_SM1 + pos] : 0.f;
            rV[j] = ok ? sm[OFF_SR1 + pos] : 0.f;
        }
        for (int k = 0; k < 8; k++) {
            const int ch = wid + 16 * k;
            const float gam = c_n1w[ch], bet = c_n1b[ch];
            const float* xc = x + xb + (long long)ch * HWn;
            #pragma unroll
            for (int j = 0; j < 8; j++) {
                int pos = lane + 32 * j;
                if (pos < NPOS) {
                    float v = 0.f;
                    if (gofs[j] >= 0) v = (xc[gofs[j]] - mV[j]) * rV[j] * gam + bet;
                    sm[OFF_SX + ch * NPOS + pos] = v;
                }
            }
        }
    }
    __syncthreads();

    {
        const int pairslot = tid & 63;
        const int px0 = pairslot & 15, py0 = (pairslot >> 4) * 2;
        const int chb = tid >> 6;
        bool myp[4], mx[3];
        #pragma unroll
        for (int k = 0; k < 4; k++) myp[k] = (unsigned)(h0 + py0 + k - 1) < (unsigned)Hn;
        #pragma unroll
        for (int d = 0; d < 3; d++)  mx[d]  = (unsigned)(w0 + px0 + d - 1) < (unsigned)Wn;

        #pragma unroll 2
        for (int it = 0; it < 16; it++) {
            const int ch = chb + it * 8;
            const int gg = ch >> 5, cc = ch & 31;
            const int srcb = ((0x2031 >> (4*gg)) & 15) << 5;
            const int offy = (0x2002 >> (4*gg)) & 15;
            const int offx = (0x2020 >> (4*gg)) & 15;
            const float* bp = sm + OFF_SX + (srcb + cc) * NPOS + (py0 + offy) * R2W + (px0 + offx);
            float aA = c_sdw_b[gg][cc], aB = aA;
            #pragma unroll
            for (int k = 0; k < 4; k++) {
                #pragma unroll
                for (int d = 0; d < 3; d++) {
                    float t = bp[k * R2W + d];
                    bool okc = myp[k] && mx[d];
                    if (k < 3 && okc) aA = fmaf(c_sdw_w[gg][cc][k*3 + d], t, aA);
                    if (k > 0 && okc) aB = fmaf(c_sdw_w[gg][cc][(k-1)*3 + d], t, aB);
                }
            }
            sm[OFF_ST + ch * 128 + py0 * 16 + px0]       = gelu_exact(aA);
            sm[OFF_ST + ch * 128 + (py0 + 1) * 16 + px0] = gelu_exact(aB);
        }
    }
    __syncthreads();

    const int g    = tid >> 7;
    const int oj   = tid & 3;
    const int qslot = (tid >> 2) & 31;
    const int qpix = qslot * 4;
    const int qy = qpix >> 4, qx = qpix & 15;

    float acc[8][4];
    #pragma unroll
    for (int j = 0; j < 8; j++) {
        float bj = sm[OFF_PWB + g * 32 + oj * 8 + j];
        acc[j][0] = bj; acc[j][1] = bj; acc[j][2] = bj; acc[j][3] = bj;
    }
    {
        const float* w2g = sm + OFF_W2 + g * 1024 + oj * 8;
        const float* stg = sm + OFF_ST + (g * 32) * 128 + qpix;
        #pragma unroll 8
        for (int c = 0; c < 32; c++) {
            float4 wa = *(const float4*)(w2g + c * 32);
            float4 wb = *(const float4*)(w2g + c * 32 + 4);
            float4 tv = *(const float4*)(stg + c * 128);
            acc[0][0]=fmaf(wa.x,tv.x,acc[0][0]); acc[0][1]=fmaf(wa.x,tv.y,acc[0][1]); acc[0][2]=fmaf(wa.x,tv.z,acc[0][2]); acc[0][3]=fmaf(wa.x,tv.w,acc[0][3]);
            acc[1][0]=fmaf(wa.y,tv.x,acc[1][0]); acc[1][1]=fmaf(wa.y,tv.y,acc[1][1]); acc[1][2]=fmaf(wa.y,tv.z,acc[1][2]); acc[1][3]=fmaf(wa.y,tv.w,acc[1][3]);
            acc[2][0]=fmaf(wa.z,tv.x,acc[2][0]); acc[2][1]=fmaf(wa.z,tv.y,acc[2][1]); acc[2][2]=fmaf(wa.z,tv.z,acc[2][2]); acc[2][3]=fmaf(wa.z,tv.w,acc[2][3]);
            acc[3][0]=fmaf(wa.w,tv.x,acc[3][0]); acc[3][1]=fmaf(wa.w,tv.y,acc[3][1]); acc[3][2]=fmaf(wa.w,tv.z,acc[3][2]); acc[3][3]=fmaf(wa.w,tv.w,acc[3][3]);
            acc[4][0]=fmaf(wb.x,tv.x,acc[4][0]); acc[4][1]=fmaf(wb.x,tv.y,acc[4][1]); acc[4][2]=fmaf(wb.x,tv.z,acc[4][2]); acc[4][3]=fmaf(wb.x,tv.w,acc[4][3]);
            acc[5][0]=fmaf(wb.y,tv.x,acc[5][0]); acc[5][1]=fmaf(wb.y,tv.y,acc[5][1]); acc[5][2]=fmaf(wb.y,tv.z,acc[5][2]); acc[5][3]=fmaf(wb.y,tv.w,acc[5][3]);
            acc[6][0]=fmaf(wb.z,tv.x,acc[6][0]); acc[6][1]=fmaf(wb.z,tv.y,acc[6][1]); acc[6][2]=fmaf(wb.z,tv.z,acc[6][2]); acc[6][3]=fmaf(wb.z,tv.w,acc[6][3]);
            acc[7][0]=fmaf(wb.w,tv.x,acc[7][0]); acc[7][1]=fmaf(wb.w,tv.y,acc[7][1]); acc[7][2]=fmaf(wb.w,tv.z,acc[7][2]); acc[7][3]=fmaf(wb.w,tv.w,acc[7][3]);
        }
    }
    #pragma unroll
    for (int j = 0; j < 8; j++) {
        const int ci = g * 32 + oj * 8 + j;
        const float* cw = sm + OFF_C5W + ci * 9;
        const float* bp = sm + OFF_SX + ci * NPOS + (qy + 1) * R2W + (qx + 1);
        const float b5 = sm[OFF_C5B + ci];
        #pragma unroll
        for (int i = 0; i < 4; i++) {
            float a5 = b5;
            #pragma unroll
            for (int k = 0; k < 9; k++)
                a5 = fmaf(cw[k], bp[(k/3)*R2W + (k%3) + i], a5);
            acc[j][i] += a5;
        }
    }
    {
        float ps[4] = {0,0,0,0}, pq[4] = {0,0,0,0};
        #pragma unroll
        for (int j = 0; j < 8; j++)
            #pragma unroll
            for (int i = 0; i < 4; i++) { ps[i] += acc[j][i]; pq[i] = fmaf(acc[j][i], acc[j][i], pq[i]); }
        #pragma unroll
        for (int d = 1; d <= 2; d <<= 1) {
            #pragma unroll
            for (int i = 0; i < 4; i++) {
                ps[i] += __shfl_xor_sync(0xFFFFFFFFu, ps[i], d);
                pq[i] += __shfl_xor_sync(0xFFFFFFFFu, pq[i], d);
            }
        }
        if (oj == 0) {
            *(float4*)&sm[OFF_RED + g * 128 + qpix]       = make_float4(ps[0], ps[1], ps[2], ps[3]);
            *(float4*)&sm[OFF_RED + 512 + g * 128 + qpix] = make_float4(pq[0], pq[1], pq[2], pq[3]);
        }
    }
    __syncthreads();
    if (tid < 128) {
        float s = 0.f, ss = 0.f;
        #pragma unroll
        for (int g2 = 0; g2 < 4; g2++) {
            s  += sm[OFF_RED + g2 * 128 + tid];
            ss += sm[OFF_RED + 512 + g2 * 128 + tid];
        }
        float m = s * (1.0f/128.0f);
        float var = fmaf(-m, m, ss * (1.0f/128.0f));
        sm[OFF_MS + tid] = m;
        sm[OFF_RS + tid] = rsqrtf(var + 1e-6f);
    }
    __syncthreads();

    float mv[4], rv[4];
    #pragma unroll
    for (int i = 0; i < 4; i++) { mv[i] = sm[OFF_MS + qpix + i]; rv[i] = sm[OFF_RS + qpix + i]; }
    const long long obase = xb + (long long)(h0 + qy) * Wn + (w0 + qx);
    #pragma unroll
    for (int j = 0; j < 8; j++) {
        const int ci = g * 32 + oj * 8 + j;
        const int ko = ((ci & 63) << 1) | (ci >> 6);
        const float gam = sm[OFF_GAM + ko], bet = sm[OFF_BET + ko];
        float4 ov;
        ov.x = fmaf((acc[j][0] - mv[0]) * rv[0], gam, bet);
        ov.y = fmaf((acc[j][1] - mv[1]) * rv[1], gam, bet);
        ov.z = fmaf((acc[j][2] - mv[2]) * rv[2], gam, bet);
        ov.w = fmaf((acc[j][3] - mv[3]) * rv[3], gam, bet);
        *(float4*)&g_y[obase + (long long)ko * HWn] = ov;
    }
}

// ================= kernel 3: dw3(gelu) + mma.sync bf16-split GEMM (1024 thr + ldmatrix) =================
#define T3W 16
#define T3H 8
#define R3H 10
#define R3W 18
#define NT3 1024
#define YCH 32                         // channels per staging chunk
#define YPOS (R3H*R3W)                 // 180
#define AS3 136                        // bf16 row stride (272B): conflict-free frags
#define SM3_AH   0
#define SM3_AL   (SM3_AH + 128*AS3*2)   // 34816
#define SM3_BH   (SM3_AL + 128*AS3*2)   // 69632
#define SM3_BL   (SM3_BH + 128*AS3*2)   // 104448
#define SM3_Y    (SM3_BL + 128*AS3*2)   // 139264: 2 x [32][180] fp32
#define SM3_BIAS (SM3_Y + 2*YCH*YPOS*4) // 185344
#define SM3_TOTAL (SM3_BIAS + 512)      // 185856 bytes

__global__ __launch_bounds__(NT3, 1) void k3_final(float* __restrict__ out)
{
    extern __shared__ char smc[];
    float* bias = (float*)(smc + SM3_BIAS);
    const int b  = blockIdx.z;
    const int h0 = blockIdx.y * T3H;
    const int w0 = blockIdx.x * T3W;
    const int tid = threadIdx.x;
    const int wid = tid >> 5, lane = tid & 31;
    const long long xb = (long long)b * CHWn;
    float* ybuf0 = (float*)(smc + SM3_Y);
    float* ybuf1 = ybuf0 + YCH * YPOS;

    // stage B hi/lo (long-latency loads issue first)
    for (int i = tid; i < 4096; i += NT3) {
        int o = i >> 5, qq = i & 31;
        *(uint2*)(smc + SM3_BH + o * (AS3*2) + qq * 8) = ((const uint2*)g_pwbh)[i];
        *(uint2*)(smc + SM3_BL + o * (AS3*2) + qq * 8) = ((const uint2*)g_pwbl)[i];
    }
    if (tid < 128) bias[tid] = c_lpwb[tid];

    // hoisted per-lane staging metadata for pos = lane + 32*j (j<6)
    int goff[6];
    #pragma unroll
    for (int j = 0; j < 6; j++) {
        int pos = lane + 32 * j;
        bool ok = pos < YPOS;
        int r = pos / R3W, cc = pos - r * R3W;
        int gh = h0 + r - 1, gw = w0 + cc - 1;
        bool inb = ok && (unsigned)gh < (unsigned)Hn && (unsigned)gw < (unsigned)Wn;
        goff[j] = inb ? (gh * Wn + gw) : -1;
    }

    // stage chunk 0 into ybuf0 (one channel per warp)
    if (wid < YCH) {
        const float* yc = g_y + xb + (long long)wid * HWn;
        float* dst = ybuf0 + wid * YPOS;
        #pragma unroll
        for (int j = 0; j < 6; j++) {
            int pos = lane + 32 * j;
            if (pos < YPOS) dst[pos] = (goff[j] >= 0) ? yc[goff[j]] : 0.f;
        }
    }
    __syncthreads();

    #pragma unroll
    for (int q = 0; q < 4; q++) {
        float* cur = (q & 1) ? ybuf1 : ybuf0;
        float* nxt = (q & 1) ? ybuf0 : ybuf1;
        // issue next chunk's loads first (overlap with compute below)
        if (q < 3 && wid < YCH) {
            const int chb = (q + 1) * YCH;
            const float* yc = g_y + xb + (long long)(chb + wid) * HWn;
            float* dst = nxt + wid * YPOS;
            #pragma unroll
            for (int j = 0; j < 6; j++) {
                int pos = lane + 32 * j;
                if (pos < YPOS) dst[pos] = (goff[j] >= 0) ? yc[goff[j]] : 0.f;
            }
        }
        // compute chunk q: 8 ch-groups (4 ch each) x 128 px = 1024 threads
        {
            const int p = tid & 127;
            const int py = p >> 4, pxx = p & 15;
            const int grp = tid >> 7;                     // 0..7, warp-uniform
            const int chl0 = grp * 4;
            const int ch0 = q * YCH + chl0;
            uint32_t hv[2], lv[2];
            #pragma unroll
            for (int j = 0; j < 4; j++) {
                const int ch = ch0 + j;
                const float* bp = cur + (chl0 + j) * YPOS + py * R3W + pxx;
                float a = c_ldwb[ch];
                #pragma unroll
                for (int k = 0; k < 9; k++)
                    a = fmaf(c_ldww[ch][k], bp[(k/3)*R3W + (k%3)], a);
                float v = gelu_exact(a);
                unsigned short hb, lb;
                bf16_split(v, hb, lb);
                if (j & 1) { hv[j >> 1] |= (uint32_t)hb << 16; lv[j >> 1] |= (uint32_t)lb << 16; }
                else       { hv[j >> 1]  = hb;                 lv[j >> 1]  = lb; }
            }
            *(uint2*)(smc + SM3_AH + p * (AS3*2) + ch0 * 2) = make_uint2(hv[0], hv[1]);
            *(uint2*)(smc + SM3_AL + p * (AS3*2) + ch0 * 2) = make_uint2(lv[0], lv[1]);
        }
        __syncthreads();
    }

    // warp GEMM: 32 warps, 16(M) x 32(N) tile each; ldmatrix fragment loads
    const int mi = wid >> 2, ni = wid & 3;     // mi 0..7 (m16), ni 0..3 (n32)
    const uint32_t smb = smem_u32(smc);
    // per-lane ldmatrix address offsets (byte), before kb and pass-base
    const uint32_t a_off = (uint32_t)(mi*16 + (lane & 15)) * (AS3*2) + ((lane >> 4) * 8) * 2;
    const uint32_t b_row = (uint32_t)(ni*32 + (lane >> 4) * 8 + (lane & 7));   // pair base added below
    const uint32_t b_off = b_row * (AS3*2) + (((lane >> 3) & 1) * 8) * 2;

    float cfr[4][4];
    #pragma unroll
    for (int t = 0; t < 4; t++) { cfr[t][0]=0.f; cfr[t][1]=0.f; cfr[t][2]=0.f; cfr[t][3]=0.f; }

    #pragma unroll
    for (int pass = 0; pass < 3; pass++) {
        const uint32_t AbO = smb + (pass == 2 ? SM3_AL : SM3_AH);
        const uint32_t BbO = smb + (pass == 1 ? SM3_BL : SM3_BH);
        #pragma unroll
        for (int k0 = 0; k0 < 8; k0++) {
            const uint32_t kb2 = (uint32_t)(k0 * 16) * 2;
            uint32_t a[4], bfr[4][2];
            ldsm_x4(a[0], a[1], a[2], a[3], AbO + a_off + kb2);
            ldsm_x4(bfr[0][0], bfr[0][1], bfr[1][0], bfr[1][1], BbO + b_off + kb2);
            ldsm_x4(bfr[2][0], bfr[2][1], bfr[3][0], bfr[3][1], BbO + b_off + 16 * (AS3*2) + kb2);
            #pragma unroll
            for (int n4 = 0; n4 < 4; n4++)
                mma16816(cfr[n4], a, bfr[n4]);
        }
    }

    // epilogue: add bias, store direct to gmem
    const int lr = lane >> 2, lc = lane & 3;
    #pragma unroll
    for (int n4 = 0; n4 < 4; n4++) {
        const float* cf = cfr[n4];
        const int p0 = mi*16 + lr;
        const int p1 = p0 + 8;
        const int oo = ni*32 + n4*8 + lc*2;
        const float b0v = bias[oo], b1v = bias[oo + 1];
        const long long r0 = xb + (long long)(h0 + (p0 >> 4)) * Wn + (w0 + (p0 & 15));
        const long long r1 = xb + (long long)(h0 + (p1 >> 4)) * Wn + (w0 + (p1 & 15));
        out[r0 + (long long)oo * HWn]       = cf[0] + b0v;
        out[r0 + (long long)(oo+1) * HWn]   = cf[1] + b1v;
        out[r1 + (long long)oo * HWn]       = cf[2] + b0v;
        out[r1 + (long long)(oo+1) * HWn]   = cf[3] + b1v;
    }
}

// ================= launch =================
extern "C" void kernel_launch(void* const* d_in, const int* in_sizes, int n_in,
                              void* d_out, int out_size)
{
    (void)out_size;
    int idx_x = 0, idx_lpw = -1, idx_c5w = -1, idx_ldww = -1;
    int dw_w[4] = {-1,-1,-1,-1}, pw_w[4] = {-1,-1,-1,-1};
    int ndw = 0, npw = 0;
    for (int i = 0; i < n_in; i++) {
        int s = in_sizes[i];
        if (s > 100000)      idx_x = i;
        else if (s == 16384) idx_lpw = i;
        else if (s == 1152)  { if (idx_c5w < 0) idx_c5w = i; else idx_ldww = i; }
        else if (s == 288 && ndw < 4)  dw_w[ndw++] = i;
        else if (s == 1024 && npw < 4) pw_w[npw++] = i;
    }
    const int idx_c5b  = idx_c5w  + 1;
    const int idx_ldwb = idx_ldww + 1;
    const int idx_lpwb = idx_lpw  + 1;
    int v128[8]; int nv = 0;
    for (int i = 0; i < n_in; i++)
        if (in_sizes[i] == 128 && i != idx_c5b && i != idx_ldwb && i != idx_lpwb && nv < 8)
            v128[nv++] = i;
    const int idx_n1w = v128[0], idx_n1b = v128[1];
    const int idx_n2w = v128[2], idx_n2b = v128[3];

    const float* x = (const float*)d_in[idx_x];

    cudaMemcpyToSymbolAsync(c_n1w, d_in[idx_n1w], Cn*4, 0, cudaMemcpyDeviceToDevice);
    cudaMemcpyToSymbolAsync(c_n1b, d_in[idx_n1b], Cn*4, 0, cudaMemcpyDeviceToDevice);
    const int GS[4] = {1, 3, 0, 2};
    for (int g = 0; g < 4; g++) {
        int sbx = GS[g];
        cudaMemcpyToSymbolAsync(c_sdw_w,  d_in[dw_w[sbx]],     32*9*4,  g*32*9*4,  cudaMemcpyDeviceToDevice);
        cudaMemcpyToSymbolAsync(c_sdw_b,  d_in[dw_w[sbx] + 1], 32*4,    g*32*4,    cudaMemcpyDeviceToDevice);
        cudaMemcpyToSymbolAsync(g_spw_w,  d_in[pw_w[sbx]],     32*32*4, g*32*32*4, cudaMemcpyDeviceToDevice);
        cudaMemcpyToSymbolAsync(g_spw_b,  d_in[pw_w[sbx] + 1], 32*4,    g*32*4,    cudaMemcpyDeviceToDevice);
    }
    cudaMemcpyToSymbolAsync(g_c5w,  d_in[idx_c5w],  Cn*9*4, 0, cudaMemcpyDeviceToDevice);
    cudaMemcpyToSymbolAsync(g_c5b,  d_in[idx_c5b],  Cn*4,   0, cudaMemcpyDeviceToDevice);
    cudaMemcpyToSymbolAsync(g_n2w,  d_in[idx_n2w],  Cn*4,   0, cudaMemcpyDeviceToDevice);
    cudaMemcpyToSymbolAsync(g_n2b,  d_in[idx_n2b],  Cn*4,   0, cudaMemcpyDeviceToDevice);
    cudaMemcpyToSymbolAsync(c_ldww, d_in[idx_ldww], Cn*9*4, 0, cudaMemcpyDeviceToDevice);
    cudaMemcpyToSymbolAsync(c_ldwb, d_in[idx_ldwb], Cn*4,   0, cudaMemcpyDeviceToDevice);
    cudaMemcpyToSymbolAsync(c_lpwb, d_in[idx_lpwb], Cn*4,   0, cudaMemcpyDeviceToDevice);

    const int smem2 = SMEM2_FLOATS * 4;
    cudaFuncSetAttribute(k2_mix,   cudaFuncAttributeMaxDynamicSharedMemorySize, smem2);
    cudaFuncSetAttribute(k3_final, cudaFuncAttributeMaxDynamicSharedMemorySize, SM3_TOTAL);

    k0_prep<<<64, 256>>>((const float*)d_in[idx_lpw]);
    k1_stats<<<NPIX/256, 256>>>(x);
    k2_mix<<<dim3(Wn/T2W, Hn/T2H, Bn), NT2, smem2>>>(x);
    k3_final<<<dim3(Wn/T3W, Hn/T3H, Bn), NT3, SM3_TOTAL>>>((float*)d_out);
}

// round 16
// speedup vs baseline: 1.1005x; 1.0442x over previous
#include <cuda_runtime.h>
#include <cuda_bf16.h>
#include <stdint.h>
#include <math.h>

#define Bn 8
#define Cn 128
#define Hn 224
#define Wn 224
#define HWn (Hn*Wn)        // 50176
#define CHWn (Cn*HWn)      // 6422528
#define NPIX (Bn*HWn)      // 401408

// ---------------- scratch (static device globals; no allocation) ----------------
__device__ float g_y[(long long)Bn*CHWn];   // LN2-normalized, shuffled tensor (205.5 MB)
__device__ float g_m1[NPIX];
__device__ float g_r1[NPIX];
__device__ float g_spw_w[4*32*32];   // [g][o][c], group order (s2,s4,s1,s3)
__device__ float g_spw_wT[4*32*32];  // [g][c][o]  (filled by k0_prep)
__device__ float g_spw_b[128];
__device__ float g_c5w[128*9];
__device__ float g_c5b[128];
__device__ float g_n2w[128];
__device__ float g_n2b[128];
// final pw weights, bf16 hi/lo split, plain [o][ch] layout (filled by k0_prep)
__device__ __align__(16) unsigned short g_pwbh[Cn*Cn];
__device__ __align__(16) unsigned short g_pwbl[Cn*Cn];

// ---------------- constant weights (warp-uniform access only) ----------------
__constant__ float c_n1w[Cn], c_n1b[Cn];
__constant__ float c_sdw_w[4][32][9];
__constant__ float c_sdw_b[4][32];
__constant__ float c_ldww[Cn][9];
__constant__ float c_ldwb[Cn];
__constant__ float c_lpwb[Cn];

__device__ __forceinline__ float gelu_exact(float x) {
    return 0.5f * x * (1.0f + erff(x * 0.70710678118654752f));
}

// split fp32 -> bf16 hi + bf16 lo
__device__ __forceinline__ void bf16_split(float v, unsigned short& hb, unsigned short& lb) {
    __nv_bfloat16 h = __float2bfloat16(v);
    float hf = __bfloat162float(h);
    __nv_bfloat16 l = __float2bfloat16(v - hf);
    hb = *(unsigned short*)&h;
    lb = *(unsigned short*)&l;
}

// warp-level bf16 MMA (sm_80+ path, valid on base sm_100)
__device__ __forceinline__ void mma16816(float* c, const uint32_t* a, const uint32_t* b) {
    asm volatile(
        "mma.sync.aligned.m16n8k16.row.col.f32.bf16.bf16.f32 "
        "{%0,%1,%2,%3}, {%4,%5,%6,%7}, {%8,%9}, {%0,%1,%2,%3};"
        : "+f"(c[0]), "+f"(c[1]), "+f"(c[2]), "+f"(c[3])
        : "r"(a[0]), "r"(a[1]), "r"(a[2]), "r"(a[3]), "r"(b[0]), "r"(b[1]));
}

// ================= kernel 0: prep weights =================
__global__ __launch_bounds__(256) void k0_prep(const float* __restrict__ pw)
{
    int i = blockIdx.x * 256 + threadIdx.x;
    if (i < Cn*Cn) {
        unsigned short hb, lb;
        bf16_split(pw[i], hb, lb);
        g_pwbh[i] = hb;      // [o][ch] row-major
        g_pwbl[i] = lb;
    }
    if (i < 4096) {
        int g = i >> 10, r = i & 1023, o = r >> 5, c = r & 31;
        g_spw_wT[g*1024 + c*32 + o] = g_spw_w[i];
    }
}

// ================= kernel 1: LN1 stats =================
__global__ __launch_bounds__(256) void k1_stats(const float* __restrict__ x)
{
    int idx = blockIdx.x * 256 + threadIdx.x;
    int b  = idx / HWn;
    int hw = idx - b * HWn;
    const float* px = x + b * CHWn + hw;
    float s = 0.f, ss = 0.f;
    #pragma unroll 8
    for (int ch = 0; ch < Cn; ch++) {
        float v = px[ch * HWn];
        s += v; ss = fmaf(v, v, ss);
    }
    float m = s * (1.0f/128.0f);
    float var = fmaf(-m, m, ss * (1.0f/128.0f));
    g_m1[idx] = m;
    g_r1[idx] = rsqrtf(var + 1e-6f);
}

// ================= kernel 2: branches + c5 + shuffle + LN2 (R13 best: 512 thr) =================
#define T2W 16
#define T2H 8
#define R2W 20
#define R2H 12
#define NPOS 240           // R2H*R2W
#define NT2 512
#define OFF_SX   0                       // [128][240]
#define OFF_ST   (OFF_SX + Cn*NPOS)      // 30720: t [128][128]
#define OFF_W2   (OFF_ST + Cn*128)       // 47104: spw_wT [4][32c][32o]
#define OFF_RED  (OFF_W2 + 4096)         // 51200: [2][4][128]
#define OFF_MS   (OFF_RED + 1024)        // 52224
#define OFF_RS   (OFF_MS + 128)
#define OFF_GAM  (OFF_RS + 128)
#define OFF_BET  (OFF_GAM + 128)
#define OFF_C5W  (OFF_BET + 128)         // [128][9]
#define OFF_C5B  (OFF_C5W + 1152)
#define OFF_PWB  (OFF_C5B + 128)
#define OFF_SM1  (OFF_PWB + 128)         // [240]
#define OFF_SR1  (OFF_SM1 + NPOS)
#define SMEM2_FLOATS (OFF_SR1 + NPOS)    // 54624 floats = 218496 B

__global__ __launch_bounds__(NT2, 1) void k2_mix(const float* __restrict__ x)
{
    extern __shared__ float sm[];
    const int b  = blockIdx.z;
    const int h0 = blockIdx.y * T2H;
    const int w0 = blockIdx.x * T2W;
    const int tid = threadIdx.x;
    const int wid = tid >> 5, lane = tid & 31;
    const long long xb = (long long)b * CHWn;

    if (tid < NPOS) {
        int r = tid / R2W, cc = tid - r * R2W;
        int gh = h0 + r - 2, gw = w0 + cc - 2;
        float m = 0.f, rs = 0.f;
        if ((unsigned)gh < (unsigned)Hn && (unsigned)gw < (unsigned)Wn) {
            int p = b * HWn + gh * Wn + gw;
            m = g_m1[p]; rs = g_r1[p];
        }
        sm[OFF_SM1 + tid] = m; sm[OFF_SR1 + tid] = rs;
    }
    for (int i = tid; i < 4096; i += NT2) sm[OFF_W2 + i] = g_spw_wT[i];
    for (int i = tid; i < 1152; i += NT2) sm[OFF_C5W + i] = g_c5w[i];
    if (tid < 128) {
        sm[OFF_C5B + tid] = g_c5b[tid];
        sm[OFF_PWB + tid] = g_spw_b[tid];
        sm[OFF_GAM + tid] = g_n2w[tid];
        sm[OFF_BET + tid] = g_n2b[tid];
    }
    __syncthreads();

    {
        int   gofs[8];
        float mV[8], rV[8];
        #pragma unroll
        for (int j = 0; j < 8; j++) {
            int pos = lane + 32 * j;
            bool ok = pos < NPOS;
            int r = pos / R2W, cc = pos - r * R2W;
            int gh = h0 + r - 2, gw = w0 + cc - 2;
            bool inb = ok && (unsigned)gh < (unsigned)Hn && (unsigned)gw < (unsigned)Wn;
            gofs[j] = inb ? (gh * Wn + gw) : -1;
            mV[j] = ok ? sm[OFF_SM1 + pos] : 0.f;
            rV[j] = ok ? sm[OFF_SR1 + pos] : 0.f;
        }
        for (int k = 0; k < 8; k++) {
            const int ch = wid + 16 * k;
            const float gam = c_n1w[ch], bet = c_n1b[ch];
            const float* xc = x + xb + (long long)ch * HWn;
            #pragma unroll
            for (int j = 0; j < 8; j++) {
                int pos = lane + 32 * j;
                if (pos < NPOS) {
                    float v = 0.f;
                    if (gofs[j] >= 0) v = (xc[gofs[j]] - mV[j]) * rV[j] * gam + bet;
                    sm[OFF_SX + ch * NPOS + pos] = v;
                }
            }
        }
    }
    __syncthreads();

    {
        const int pairslot = tid & 63;
        const int px0 = pairslot & 15, py0 = (pairslot >> 4) * 2;
        const int chb = tid >> 6;
        bool myp[4], mx[3];
        #pragma unroll
        for (int k = 0; k < 4; k++) myp[k] = (unsigned)(h0 + py0 + k - 1) < (unsigned)Hn;
        #pragma unroll
        for (int d = 0; d < 3; d++)  mx[d]  = (unsigned)(w0 + px0 + d - 1) < (unsigned)Wn;

        #pragma unroll 2
        for (int it = 0; it < 16; it++) {
            const int ch = chb + it * 8;
            const int gg = ch >> 5, cc = ch & 31;
            const int srcb = ((0x2031 >> (4*gg)) & 15) << 5;
            const int offy = (0x2002 >> (4*gg)) & 15;
            const int offx = (0x2020 >> (4*gg)) & 15;
            const float* bp = sm + OFF_SX + (srcb + cc) * NPOS + (py0 + offy) * R2W + (px0 + offx);
            float aA = c_sdw_b[gg][cc], aB = aA;
            #pragma unroll
            for (int k = 0; k < 4; k++) {
                #pragma unroll
                for (int d = 0; d < 3; d++) {
                    float t = bp[k * R2W + d];
                    bool okc = myp[k] && mx[d];
                    if (k < 3 && okc) aA = fmaf(c_sdw_w[gg][cc][k*3 + d], t, aA);
                    if (k > 0 && okc) aB = fmaf(c_sdw_w[gg][cc][(k-1)*3 + d], t, aB);
                }
            }
            sm[OFF_ST + ch * 128 + py0 * 16 + px0]       = gelu_exact(aA);
            sm[OFF_ST + ch * 128 + (py0 + 1) * 16 + px0] = gelu_exact(aB);
        }
    }
    __syncthreads();

    const int g    = tid >> 7;
    const int oj   = tid & 3;
    const int qslot = (tid >> 2) & 31;
    const int qpix = qslot * 4;
    const int qy = qpix >> 4, qx = qpix & 15;

    float acc[8][4];
    #pragma unroll
    for (int j = 0; j < 8; j++) {
        float bj = sm[OFF_PWB + g * 32 + oj * 8 + j];
        acc[j][0] = bj; acc[j][1] = bj; acc[j][2] = bj; acc[j][3] = bj;
    }
    {
        const float* w2g = sm + OFF_W2 + g * 1024 + oj * 8;
        const float* stg = sm + OFF_ST + (g * 32) * 128 + qpix;
        #pragma unroll 8
        for (int c = 0; c < 32; c++) {
            float4 wa = *(const float4*)(w2g + c * 32);
            float4 wb = *(const float4*)(w2g + c * 32 + 4);
            float4 tv = *(const float4*)(stg + c * 128);
            acc[0][0]=fmaf(wa.x,tv.x,acc[0][0]); acc[0][1]=fmaf(wa.x,tv.y,acc[0][1]); acc[0][2]=fmaf(wa.x,tv.z,acc[0][2]); acc[0][3]=fmaf(wa.x,tv.w,acc[0][3]);
            acc[1][0]=fmaf(wa.y,tv.x,acc[1][0]); acc[1][1]=fmaf(wa.y,tv.y,acc[1][1]); acc[1][2]=fmaf(wa.y,tv.z,acc[1][2]); acc[1][3]=fmaf(wa.y,tv.w,acc[1][3]);
            acc[2][0]=fmaf(wa.z,tv.x,acc[2][0]); acc[2][1]=fmaf(wa.z,tv.y,acc[2][1]); acc[2][2]=fmaf(wa.z,tv.z,acc[2][2]); acc[2][3]=fmaf(wa.z,tv.w,acc[2][3]);
            acc[3][0]=fmaf(wa.w,tv.x,acc[3][0]); acc[3][1]=fmaf(wa.w,tv.y,acc[3][1]); acc[3][2]=fmaf(wa.w,tv.z,acc[3][2]); acc[3][3]=fmaf(wa.w,tv.w,acc[3][3]);
            acc[4][0]=fmaf(wb.x,tv.x,acc[4][0]); acc[4][1]=fmaf(wb.x,tv.y,acc[4][1]); acc[4][2]=fmaf(wb.x,tv.z,acc[4][2]); acc[4][3]=fmaf(wb.x,tv.w,acc[4][3]);
            acc[5][0]=fmaf(wb.y,tv.x,acc[5][0]); acc[5][1]=fmaf(wb.y,tv.y,acc[5][1]); acc[5][2]=fmaf(wb.y,tv.z,acc[5][2]); acc[5][3]=fmaf(wb.y,tv.w,acc[5][3]);
            acc[6][0]=fmaf(wb.z,tv.x,acc[6][0]); acc[6][1]=fmaf(wb.z,tv.y,acc[6][1]); acc[6][2]=fmaf(wb.z,tv.z,acc[6][2]); acc[6][3]=fmaf(wb.z,tv.w,acc[6][3]);
            acc[7][0]=fmaf(wb.w,tv.x,acc[7][0]); acc[7][1]=fmaf(wb.w,tv.y,acc[7][1]); acc[7][2]=fmaf(wb.w,tv.z,acc[7][2]); acc[7][3]=fmaf(wb.w,tv.w,acc[7][3]);
        }
    }
    #pragma unroll
    for (int j = 0; j < 8; j++) {
        const int ci = g * 32 + oj * 8 + j;
        const float* cw = sm + OFF_C5W + ci * 9;
        const float* bp = sm + OFF_SX + ci * NPOS + (qy + 1) * R2W + (qx + 1);
        const float b5 = sm[OFF_C5B + ci];
        #pragma unroll
        for (int i = 0; i < 4; i++) {
            float a5 = b5;
            #pragma unroll
            for (int k = 0; k < 9; k++)
                a5 = fmaf(cw[k], bp[(k/3)*R2W + (k%3) + i], a5);
            acc[j][i] += a5;
        }
    }
    {
        float ps[4] = {0,0,0,0}, pq[4] = {0,0,0,0};
        #pragma unroll
        for (int j = 0; j < 8; j++)
            #pragma unroll
            for (int i = 0; i < 4; i++) { ps[i] += acc[j][i]; pq[i] = fmaf(acc[j][i], acc[j][i], pq[i]); }
        #pragma unroll
        for (int d = 1; d <= 2; d <<= 1) {
            #pragma unroll
            for (int i = 0; i < 4; i++) {
                ps[i] += __shfl_xor_sync(0xFFFFFFFFu, ps[i], d);
                pq[i] += __shfl_xor_sync(0xFFFFFFFFu, pq[i], d);
            }
        }
        if (oj == 0) {
            *(float4*)&sm[OFF_RED + g * 128 + qpix]       = make_float4(ps[0], ps[1], ps[2], ps[3]);
            *(float4*)&sm[OFF_RED + 512 + g * 128 + qpix] = make_float4(pq[0], pq[1], pq[2], pq[3]);
        }
    }
    __syncthreads();
    if (tid < 128) {
        float s = 0.f, ss = 0.f;
        #pragma unroll
        for (int g2 = 0; g2 < 4; g2++) {
            s  += sm[OFF_RED + g2 * 128 + tid];
            ss += sm[OFF_RED + 512 + g2 * 128 + tid];
        }
        float m = s * (1.0f/128.0f);
        float var = fmaf(-m, m, ss * (1.0f/128.0f));
        sm[OFF_MS + tid] = m;
        sm[OFF_RS + tid] = rsqrtf(var + 1e-6f);
    }
    __syncthreads();

    float mv[4], rv[4];
    #pragma unroll
    for (int i = 0; i < 4; i++) { mv[i] = sm[OFF_MS + qpix + i]; rv[i] = sm[OFF_RS + qpix + i]; }
    const long long obase = xb + (long long)(h0 + qy) * Wn + (w0 + qx);
    #pragma unroll
    for (int j = 0; j < 8; j++) {
        const int ci = g * 32 + oj * 8 + j;
        const int ko = ((ci & 63) << 1) | (ci >> 6);
        const float gam = sm[OFF_GAM + ko], bet = sm[OFF_BET + ko];
        float4 ov;
        ov.x = fmaf((acc[j][0] - mv[0]) * rv[0], gam, bet);
        ov.y = fmaf((acc[j][1] - mv[1]) * rv[1], gam, bet);
        ov.z = fmaf((acc[j][2] - mv[2]) * rv[2], gam, bet);
        ov.w = fmaf((acc[j][3] - mv[3]) * rv[3], gam, bet);
        *(float4*)&g_y[obase + (long long)ko * HWn] = ov;
    }
}

// ================= kernel 3: dw3(gelu) + mma.sync bf16-split GEMM (R14 best: 1024 thr, plain LDS) =================
#define T3W 16
#define T3H 8
#define R3H 10
#define R3W 18
#define NT3 1024
#define YCH 32                         // channels per staging chunk
#define YPOS (R3H*R3W)                 // 180
#define AS3 136                        // bf16 row stride (272B): conflict-free frags
#define SM3_AH   0
#define SM3_AL   (SM3_AH + 128*AS3*2)   // 34816
#define SM3_BH   (SM3_AL + 128*AS3*2)   // 69632
#define SM3_BL   (SM3_BH + 128*AS3*2)   // 104448
#define SM3_Y    (SM3_BL + 128*AS3*2)   // 139264: 2 x [32][180] fp32
#define SM3_BIAS (SM3_Y + 2*YCH*YPOS*4) // 185344
#define SM3_TOTAL (SM3_BIAS + 512)      // 185856 bytes

__global__ __launch_bounds__(NT3, 1) void k3_final(float* __restrict__ out)
{
    extern __shared__ char smc[];
    float* bias = (float*)(smc + SM3_BIAS);
    const int b  = blockIdx.z;
    const int h0 = blockIdx.y * T3H;
    const int w0 = blockIdx.x * T3W;
    const int tid = threadIdx.x;
    const int wid = tid >> 5, lane = tid & 31;
    const long long xb = (long long)b * CHWn;
    float* ybuf0 = (float*)(smc + SM3_Y);
    float* ybuf1 = ybuf0 + YCH * YPOS;

    // stage B hi/lo (long-latency loads issue first)
    for (int i = tid; i < 4096; i += NT3) {
        int o = i >> 5, qq = i & 31;
        *(uint2*)(smc + SM3_BH + o * (AS3*2) + qq * 8) = ((const uint2*)g_pwbh)[i];
        *(uint2*)(smc + SM3_BL + o * (AS3*2) + qq * 8) = ((const uint2*)g_pwbl)[i];
    }
    if (tid < 128) bias[tid] = c_lpwb[tid];

    // hoisted per-lane staging metadata for pos = lane + 32*j (j<6)
    int goff[6];
    #pragma unroll
    for (int j = 0; j < 6; j++) {
        int pos = lane + 32 * j;
        bool ok = pos < YPOS;
        int r = pos / R3W, cc = pos - r * R3W;
        int gh = h0 + r - 1, gw = w0 + cc - 1;
        bool inb = ok && (unsigned)gh < (unsigned)Hn && (unsigned)gw < (unsigned)Wn;
        goff[j] = inb ? (gh * Wn + gw) : -1;
    }

    // stage chunk 0 into ybuf0 (one channel per warp)
    if (wid < YCH) {
        const float* yc = g_y + xb + (long long)wid * HWn;
        float* dst = ybuf0 + wid * YPOS;
        #pragma unroll
        for (int j = 0; j < 6; j++) {
            int pos = lane + 32 * j;
            if (pos < YPOS) dst[pos] = (goff[j] >= 0) ? yc[goff[j]] : 0.f;
        }
    }
    __syncthreads();

    #pragma unroll
    for (int q = 0; q < 4; q++) {
        float* cur = (q & 1) ? ybuf1 : ybuf0;
        float* nxt = (q & 1) ? ybuf0 : ybuf1;
        // issue next chunk's loads first (overlap with compute below)
        if (q < 3 && wid < YCH) {
            const int chb = (q + 1) * YCH;
            const float* yc = g_y + xb + (long long)(chb + wid) * HWn;
            float* dst = nxt + wid * YPOS;
            #pragma unroll
            for (int j = 0; j < 6; j++) {
                int pos = lane + 32 * j;
                if (pos < YPOS) dst[pos] = (goff[j] >= 0) ? yc[goff[j]] : 0.f;
            }
        }
        // compute chunk q: 8 ch-groups (4 ch each) x 128 px = 1024 threads
        {
            const int p = tid & 127;
            const int py = p >> 4, pxx = p & 15;
            const int grp = tid >> 7;                     // 0..7, warp-uniform
            const int chl0 = grp * 4;
            const int ch0 = q * YCH + chl0;
            uint32_t hv[2], lv[2];
            #pragma unroll
            for (int j = 0; j < 4; j++) {
                const int ch = ch0 + j;
                const float* bp = cur + (chl0 + j) * YPOS + py * R3W + pxx;
                float a = c_ldwb[ch];
                #pragma unroll
                for (int k = 0; k < 9; k++)
                    a = fmaf(c_ldww[ch][k], bp[(k/3)*R3W + (k%3)], a);
                float v = gelu_exact(a);
                unsigned short hb, lb;
                bf16_split(v, hb, lb);
                if (j & 1) { hv[j >> 1] |= (uint32_t)hb << 16; lv[j >> 1] |= (uint32_t)lb << 16; }
                else       { hv[j >> 1]  = hb;                 lv[j >> 1]  = lb; }
            }
            *(uint2*)(smc + SM3_AH + p * (AS3*2) + ch0 * 2) = make_uint2(hv[0], hv[1]);
            *(uint2*)(smc + SM3_AL + p * (AS3*2) + ch0 * 2) = make_uint2(lv[0], lv[1]);
        }
        __syncthreads();
    }

    // warp GEMM: 32 warps, 16(M) x 32(N) tile each; 3 passes (AhBh, AhBl, AlBh)
    const int mi = wid >> 2, ni = wid & 3;     // mi 0..7 (m16), ni 0..3 (n32)
    const int lr = lane >> 2, lc = lane & 3;
    float cfr[4][4];
    #pragma unroll
    for (int t = 0; t < 4; t++) { cfr[t][0]=0.f; cfr[t][1]=0.f; cfr[t][2]=0.f; cfr[t][3]=0.f; }

    #pragma unroll
    for (int pass = 0; pass < 3; pass++) {
        const char* Ab = smc + (pass == 2 ? SM3_AL : SM3_AH);
        const char* Bb = smc + (pass == 1 ? SM3_BL : SM3_BH);
        #pragma unroll
        for (int k0 = 0; k0 < 8; k0++) {
            const int kb = k0 * 16;
            uint32_t a[4], bfr[4][2];
            {
                const char* ap = Ab + (mi*16 + lr) * (AS3*2) + (kb + lc*2) * 2;
                a[0] = *(const uint32_t*)(ap);
                a[1] = *(const uint32_t*)(ap + 8 * (AS3*2));
                a[2] = *(const uint32_t*)(ap + 16);
                a[3] = *(const uint32_t*)(ap + 8 * (AS3*2) + 16);
            }
            #pragma unroll
            for (int n4 = 0; n4 < 4; n4++) {
                const char* bp = Bb + (ni*32 + n4*8 + lr) * (AS3*2) + (kb + lc*2) * 2;
                bfr[n4][0] = *(const uint32_t*)(bp);
                bfr[n4][1] = *(const uint32_t*)(bp + 16);
            }
            #pragma unroll
            for (int n4 = 0; n4 < 4; n4++)
                mma16816(cfr[n4], a, bfr[n4]);
        }
    }

    // epilogue: add bias, store direct to gmem
    #pragma unroll
    for (int n4 = 0; n4 < 4; n4++) {
        const float* cf = cfr[n4];
        const int p0 = mi*16 + lr;
        const int p1 = p0 + 8;
        const int oo = ni*32 + n4*8 + lc*2;
        const float b0v = bias[oo], b1v = bias[oo + 1];
        const long long r0 = xb + (long long)(h0 + (p0 >> 4)) * Wn + (w0 + (p0 & 15));
        const long long r1 = xb + (long long)(h0 + (p1 >> 4)) * Wn + (w0 + (p1 & 15));
        out[r0 + (long long)oo * HWn]       = cf[0] + b0v;
        out[r0 + (long long)(oo+1) * HWn]   = cf[1] + b1v;
        out[r1 + (long long)oo * HWn]       = cf[2] + b0v;
        out[r1 + (long long)(oo+1) * HWn]   = cf[3] + b1v;
    }
}

// ================= launch =================
extern "C" void kernel_launch(void* const* d_in, const int* in_sizes, int n_in,
                              void* d_out, int out_size)
{
    (void)out_size;
    int idx_x = 0, idx_lpw = -1, idx_c5w = -1, idx_ldww = -1;
    int dw_w[4] = {-1,-1,-1,-1}, pw_w[4] = {-1,-1,-1,-1};
    int ndw = 0, npw = 0;
    for (int i = 0; i < n_in; i++) {
        int s = in_sizes[i];
        if (s > 100000)      idx_x = i;
        else if (s == 16384) idx_lpw = i;
        else if (s == 1152)  { if (idx_c5w < 0) idx_c5w = i; else idx_ldww = i; }
        else if (s == 288 && ndw < 4)  dw_w[ndw++] = i;
        else if (s == 1024 && npw < 4) pw_w[npw++] = i;
    }
    const int idx_c5b  = idx_c5w  + 1;
    const int idx_ldwb = idx_ldww + 1;
    const int idx_lpwb = idx_lpw  + 1;
    int v128[8]; int nv = 0;
    for (int i = 0; i < n_in; i++)
        if (in_sizes[i] == 128 && i != idx_c5b && i != idx_ldwb && i != idx_lpwb && nv < 8)
            v128[nv++] = i;
    const int idx_n1w = v128[0], idx_n1b = v128[1];
    const int idx_n2w = v128[2], idx_n2b = v128[3];

    const float* x = (const float*)d_in[idx_x];

    cudaMemcpyToSymbolAsync(c_n1w, d_in[idx_n1w], Cn*4, 0, cudaMemcpyDeviceToDevice);
    cudaMemcpyToSymbolAsync(c_n1b, d_in[idx_n1b], Cn*4, 0, cudaMemcpyDeviceToDevice);
    const int GS[4] = {1, 3, 0, 2};
    for (int g = 0; g < 4; g++) {
        int sbx = GS[g];
        cudaMemcpyToSymbolAsync(c_sdw_w,  d_in[dw_w[sbx]],     32*9*4,  g*32*9*4,  cudaMemcpyDeviceToDevice);
        cudaMemcpyToSymbolAsync(c_sdw_b,  d_in[dw_w[sbx] + 1], 32*4,    g*32*4,    cudaMemcpyDeviceToDevice);
        cudaMemcpyToSymbolAsync(g_spw_w,  d_in[pw_w[sbx]],     32*32*4, g*32*32*4, cudaMemcpyDeviceToDevice);
        cudaMemcpyToSymbolAsync(g_spw_b,  d_in[pw_w[sbx] + 1], 32*4,    g*32*4,    cudaMemcpyDeviceToDevice);
    }
    cudaMemcpyToSymbolAsync(g_c5w,  d_in[idx_c5w],  Cn*9*4, 0, cudaMemcpyDeviceToDevice);
    cudaMemcpyToSymbolAsync(g_c5b,  d_in[idx_c5b],  Cn*4,   0, cudaMemcpyDeviceToDevice);
    cudaMemcpyToSymbolAsync(g_n2w,  d_in[idx_n2w],  Cn*4,   0, cudaMemcpyDeviceToDevice);
    cudaMemcpyToSymbolAsync(g_n2b,  d_in[idx_n2b],  Cn*4,   0, cudaMemcpyDeviceToDevice);
    cudaMemcpyToSymbolAsync(c_ldww, d_in[idx_ldww], Cn*9*4, 0, cudaMemcpyDeviceToDevice);
    cudaMemcpyToSymbolAsync(c_ldwb, d_in[idx_ldwb], Cn*4,   0, cudaMemcpyDeviceToDevice);
    cudaMemcpyToSymbolAsync(c_lpwb, d_in[idx_lpwb], Cn*4,   0, cudaMemcpyDeviceToDevice);

    const int smem2 = SMEM2_FLOATS * 4;
    cudaFuncSetAttribute(k2_mix,   cudaFuncAttributeMaxDynamicSharedMemorySize, smem2);
    cudaFuncSetAttribute(k3_final, cudaFuncAttributeMaxDynamicSharedMemorySize, SM3_TOTAL);

    k0_prep<<<64, 256>>>((const float*)d_in[idx_lpw]);
    k1_stats<<<NPIX/256, 256>>>(x);
    k2_mix<<<dim3(Wn/T2W, Hn/T2H, Bn), NT2, smem2>>>(x);
    k3_final<<<dim3(Wn/T3W, Hn/T3H, Bn), NT3, SM3_TOTAL>>>((float*)d_out);
}